// round 12
// baseline (speedup 1.0000x reference)
#include <cuda_runtime.h>
#include <cuda_fp16.h>
#include <cstdint>

#define BATCH 64
#define CIN   64
#define NNODE 4097
#define TNODE 4096
#define HID   128
#define LAT   64
#define NINST 128
#define NTILE 32                 // 4096 nodes / 128-node tiles
#define LNE   (NNODE*HID)
#define SMSH  72                 // smem row stride in halves (144B, LDSM conflict-free)
#define DSMEM_BYTES (4 * 128 * SMSH * 2)   // 73728 B
#define TILE_STEP (16 * SMSH * 2)   // bytes between 16-row tiles in smem
#define STDS  136                // epilogue staging stride in halves (272B)

// ---------------- scratch ----------------------------------------------------
__device__ __half g_xt [(size_t)NINST * NNODE * CIN];
__device__ __half g_y1 [(size_t)NINST * NNODE * HID];
__device__ __half g_Wa1[2 * HID * 3 * CIN];    // [enc][o][k], k = k3*C + c
__device__ __half g_Wa2[2 * HID * 3 * HID];
__device__ float g_part1[NINST * NTILE * 2];
__device__ float g_part2[NINST * NTILE * 2];
__device__ float g_st1[NINST * 2];
__device__ float g_st2[NINST * 2];
__device__ float g_pmax[NINST * NTILE * HID];

__device__ __forceinline__ void mma_f16(float* d, const uint32_t* a, uint32_t b0, uint32_t b1) {
    asm volatile(
        "mma.sync.aligned.m16n8k16.row.col.f32.f16.f16.f32 "
        "{%0,%1,%2,%3}, {%4,%5,%6,%7}, {%8,%9}, {%0,%1,%2,%3};"
        : "+f"(d[0]), "+f"(d[1]), "+f"(d[2]), "+f"(d[3])
        : "r"(a[0]), "r"(a[1]), "r"(a[2]), "r"(a[3]), "r"(b0), "r"(b1));
}
__device__ __forceinline__ void ldsm4(uint32_t* r, uint32_t addr) {
    asm volatile("ldmatrix.sync.aligned.m8n8.x4.shared.b16 {%0,%1,%2,%3}, [%4];"
                 : "=r"(r[0]), "=r"(r[1]), "=r"(r[2]), "=r"(r[3]) : "r"(addr));
}
__device__ __forceinline__ void stsm4t(uint32_t addr, uint32_t r0, uint32_t r1,
                                       uint32_t r2, uint32_t r3) {
    asm volatile("stmatrix.sync.aligned.m8n8.x4.trans.shared.b16 [%0], {%1,%2,%3,%4};"
                 :: "r"(addr), "r"(r0), "r"(r1), "r"(r2), "r"(r3) : "memory");
}
__device__ __forceinline__ uint32_t smem_u32(const void* p) {
    uint32_t a;
    asm("{ .reg .u64 t; cvta.to.shared.u64 t, %1; cvt.u32.u64 %0, t; }" : "=r"(a) : "l"(p));
    return a;
}
__device__ __forceinline__ void cp16(uint32_t dst, const void* src) {
    asm volatile("cp.async.cg.shared.global [%0], [%1], 16;" :: "r"(dst), "l"(src));
}
__device__ __forceinline__ void cp_commit() { asm volatile("cp.async.commit_group;"); }
template <int N>
__device__ __forceinline__ void cp_wait() { asm volatile("cp.async.wait_group %0;" :: "n"(N)); }
__device__ __forceinline__ uint32_t packh2(float x, float y) {
    __half2 h = __floats2half2_rn(x, y);
    return *reinterpret_cast<const uint32_t*>(&h);
}

// ---------------- weight reorder + fp16 round (two launches for ncu indexing)
__global__ void prep_weights1(const float* __restrict__ Wl1, const float* __restrict__ Wp1) {
    int idx = blockIdx.x * blockDim.x + threadIdx.x;
    int stride = gridDim.x * blockDim.x;
    for (int i = idx; i < 2 * HID * 3 * CIN; i += stride) {
        int enc = i / (HID * 3 * CIN);
        int rem = i % (HID * 3 * CIN);
        int o = rem / (3 * CIN), k = rem % (3 * CIN);
        int k3 = k / CIN, c = k % CIN;
        g_Wa1[i] = __float2half_rn((enc ? Wp1 : Wl1)[(o * CIN + c) * 3 + k3]);
    }
}
__global__ void prep_weights2(const float* __restrict__ Wl2, const float* __restrict__ Wp2) {
    int idx = blockIdx.x * blockDim.x + threadIdx.x;
    int stride = gridDim.x * blockDim.x;
    for (int i = idx; i < 2 * HID * 3 * HID; i += stride) {
        int enc = i / (HID * 3 * HID);
        int rem = i % (HID * 3 * HID);
        int o = rem / (3 * HID), k = rem % (3 * HID);
        int k3 = k / HID, c = k % HID;
        g_Wa2[i] = __float2half_rn((enc ? Wp2 : Wl2)[(o * HID + c) * 3 + k3]);
    }
}

// ---------------- transpose feats (B,C,N)->(inst,N,C), fp16 ------------------
__global__ void transpose_kernel(const float* __restrict__ lf, const float* __restrict__ pf) {
    __shared__ float tile[32][33];
    int inst = blockIdx.z;
    int enc = inst >> 6, b = inst & 63;
    const float* src = (enc ? pf : lf) + (size_t)b * CIN * NNODE;
    int n0 = blockIdx.x * 32, c0 = blockIdx.y * 32;
    for (int i = threadIdx.y; i < 32; i += 8) {
        int c = c0 + i, n = n0 + threadIdx.x;
        if (c < CIN && n < NNODE) tile[i][threadIdx.x] = src[(size_t)c * NNODE + n];
    }
    __syncthreads();
    __half* dst = g_xt + (size_t)inst * NNODE * CIN;
    for (int i = threadIdx.y; i < 32; i += 8) {
        int n = n0 + i, c = c0 + threadIdx.x;
        if (n < NNODE && c < CIN)
            dst[(size_t)n * CIN + c] = __float2half_rn(tile[threadIdx.x][i]);
    }
}

// ---------------- tensor-core tree conv (fp16 mma + ldmatrix, K=64 chunks) ---
// D[m][n] = sum_k W[m][k] * G[n][k];  8 warps, warp tile 64(M)x32(N)
// LN+relu (conv2) applied to B *fragments* after ldmatrix — bit-identical to
// applying before the smem store, but removes the LDG->reg->STS path.
template <int C, bool LN>
__global__ void __launch_bounds__(256, 2) conv_tc(
        const __half* __restrict__ xin, const __half* __restrict__ Wa,
        const float* __restrict__ bias0, const float* __restrict__ bias1,
        const int* __restrict__ children,
        const float* __restrict__ stats,
        __half* __restrict__ yout,           // conv1: raw fp16 output; conv2: null
        float* __restrict__ part,            // per-tile (sum, sumsq)
        float* __restrict__ pmax) {          // conv2: per-tile per-channel max
    constexpr int K = 3 * C;
    constexpr int NCH = K / 64;              // 64-half K chunks

    extern __shared__ __half dynH[];
    __half* sAbuf[2] = { dynH,                 dynH + 128 * SMSH };
    __half* sBbuf[2] = { dynH + 2 * 128 * SMSH, dynH + 3 * 128 * SMSH };
    __shared__ int   sCh[384];
    __shared__ float sRs[256], sRq[256];
    __shared__ float sMax[4][128];

    const int tid = threadIdx.x;
    const int w = tid >> 5, lane = tid & 31;
    const int g = lane >> 2, t = lane & 3;
    const int wm = w >> 2, wn = w & 3;
    const int mbase = wm * 64, nbase = wn * 32;

    // ldmatrix address roles (mapping verified in R8/R9 runs)
    const int lr = lane & 7, lm = lane >> 3;
    const int arow = ((lm & 1) << 3) + lr, acol = (lm >> 1) << 3;
    const int brow = ((lm >> 1) << 3) + lr, bcol = (lm & 1) << 3;
    const uint32_t aRel = ((mbase + arow) * SMSH + acol) * 2;
    const uint32_t bRel = ((nbase + brow) * SMSH + bcol) * 2;

    const int enc = blockIdx.z, b = blockIdx.y, tile = blockIdx.x;
    const int inst = enc * BATCH + b;
    const int n0 = 1 + tile * 128;

    const int* csrc = children + (size_t)b * 3 * TNODE + 3 * (n0 - 1);
    sCh[tid] = csrc[tid];
    if (tid < 128) sCh[256 + tid] = csrc[256 + tid];

    float mean = 0.f, inv = 0.f;
    if (LN) { mean = stats[inst * 2 + 0]; inv = stats[inst * 2 + 1]; }

    const __half* xb = xin + (size_t)inst * NNODE * C;
    const __half* Wb = Wa + (size_t)enc * HID * K;
    const float* bb = enc ? bias1 : bias0;

    const int row = tid >> 1, hsel = tid & 1;     // fill role: row x 32-half half
    const uint32_t aAddr[2] = { smem_u32(sAbuf[0]) + (row * SMSH + hsel * 32) * 2,
                                smem_u32(sAbuf[1]) + (row * SMSH + hsel * 32) * 2 };
    const uint32_t bAddr[2] = { smem_u32(sBbuf[0]) + (row * SMSH + hsel * 32) * 2,
                                smem_u32(sBbuf[1]) + (row * SMSH + hsel * 32) * 2 };

    float acc[4][4][4];
#pragma unroll
    for (int mi = 0; mi < 4; mi++)
#pragma unroll
        for (int ni = 0; ni < 4; ni++)
#pragma unroll
            for (int r = 0; r < 4; r++) acc[mi][ni][r] = 0.f;

    __syncthreads();   // sCh ready

    // ---- fill helpers (64-half chunks) --------------------------------------
    auto fillA = [&](int ck, int buf) {
        const __half* src = Wb + (size_t)row * K + ck * 64 + hsel * 32;
#pragma unroll
        for (int j = 0; j < 4; j++) cp16(aAddr[buf] + j * 16, src + j * 8);
    };
    auto fillB = [&](int ck, int buf) {           // raw fp16 copy (both convs)
        const int kch = (ck * 64) / C, cb = (ck * 64) % C;
        const int chd = sCh[row * 3 + kch];
        const __half* src = xb + (size_t)chd * C + cb + hsel * 32;
#pragma unroll
        for (int j = 0; j < 4; j++) cp16(bAddr[buf] + j * 16, src + j * 8);
    };
    auto lnfrag = [&](uint32_t v) -> uint32_t {   // LN+relu on a half2 fragment reg
        __half2 h = *reinterpret_cast<const __half2*>(&v);
        float2 f = __half22float2(h);
        f.x = fmaxf((f.x - mean) * inv, 0.f);
        f.y = fmaxf((f.y - mean) * inv, 0.f);
        return packh2(f.x, f.y);
    };
    auto mmaChunk = [&](int buf) {
        const uint32_t aB = smem_u32(sAbuf[buf]) + aRel;
        const uint32_t bB = smem_u32(sBbuf[buf]) + bRel;
#pragma unroll
        for (int ks = 0; ks < 4; ks++) {
            uint32_t af[4][4], bf[2][4];
#pragma unroll
            for (int mi = 0; mi < 4; mi++) ldsm4(af[mi], aB + mi * TILE_STEP + ks * 32);
#pragma unroll
            for (int p = 0; p < 2; p++) {
                ldsm4(bf[p], bB + p * TILE_STEP + ks * 32);
                if (LN) {
#pragma unroll
                    for (int q = 0; q < 4; q++) bf[p][q] = lnfrag(bf[p][q]);
                }
            }
#pragma unroll
            for (int mi = 0; mi < 4; mi++)
#pragma unroll
                for (int p = 0; p < 2; p++) {
                    mma_f16(acc[mi][2 * p + 0], af[mi], bf[p][0], bf[p][1]);
                    mma_f16(acc[mi][2 * p + 1], af[mi], bf[p][2], bf[p][3]);
                }
        }
    };

    // ---- pipelined main loop (identical for both convs) ---------------------
    fillA(0, 0); fillB(0, 0); cp_commit();
#pragma unroll 1
    for (int ck = 0; ck < NCH; ck++) {
        if (ck + 1 < NCH) {
            fillA(ck + 1, (ck + 1) & 1);
            fillB(ck + 1, (ck + 1) & 1);
            cp_commit();
            cp_wait<1>();
        } else cp_wait<0>();
        __syncthreads();
        mmaChunk(ck & 1);
        __syncthreads();
    }

    // ---------------- epilogue ------------------------------------------------
    float bv[4][2];
#pragma unroll
    for (int mi = 0; mi < 4; mi++) {
        bv[mi][0] = bb[mbase + mi * 16 + g];
        bv[mi][1] = bb[mbase + mi * 16 + g + 8];
    }
    float lsum = 0.f, lsq = 0.f;

    if (yout) {
        // stage D (with bias, fp16) into smem node-major via stmatrix.trans,
        // then write y1 with coalesced 128B rows.
        const uint32_t stBase = smem_u32(dynH);
        // per-lane stmatrix target: matrix lm -> (ni offset lm>>1, m-half lm&1)
        const uint32_t stRel = ((uint32_t)(nbase + ((lm >> 1) << 3) + lr) * STDS
                                + mbase + ((lm & 1) << 3)) * 2;
#pragma unroll
        for (int mi = 0; mi < 4; mi++)
#pragma unroll
            for (int np = 0; np < 2; np++) {
                const int ni0 = 2 * np, ni1 = 2 * np + 1;
                float v00 = acc[mi][ni0][0] + bv[mi][0], v01 = acc[mi][ni0][1] + bv[mi][0];
                float v02 = acc[mi][ni0][2] + bv[mi][1], v03 = acc[mi][ni0][3] + bv[mi][1];
                float v10 = acc[mi][ni1][0] + bv[mi][0], v11 = acc[mi][ni1][1] + bv[mi][0];
                float v12 = acc[mi][ni1][2] + bv[mi][1], v13 = acc[mi][ni1][3] + bv[mi][1];
                lsum += v00 + v01 + v02 + v03 + v10 + v11 + v12 + v13;
                lsq  += v00*v00 + v01*v01 + v02*v02 + v03*v03
                      + v10*v10 + v11*v11 + v12*v12 + v13*v13;
                stsm4t(stBase + stRel + (np * 16 * STDS + mi * 16) * 2,
                       packh2(v00, v01), packh2(v02, v03),
                       packh2(v10, v11), packh2(v12, v13));
            }
        __syncthreads();
        {
            const int rr = tid >> 1, hh = tid & 1;      // node row, 64-half half
            __half* yb = yout + ((size_t)inst * NNODE + n0 + rr) * HID + hh * 64;
            const uint4* s = reinterpret_cast<const uint4*>(dynH + rr * STDS + hh * 64);
            uint4* d = reinterpret_cast<uint4*>(yb);
#pragma unroll
            for (int j = 0; j < 8; j++) d[j] = s[j];
        }
        if (tile == 0 && tid < 16)
            reinterpret_cast<float4*>(yout + (size_t)inst * NNODE * HID)[tid] =
                make_float4(0.f, 0.f, 0.f, 0.f);
    } else {
        float mx[4][2];
#pragma unroll
        for (int mi = 0; mi < 4; mi++) { mx[mi][0] = -3.4e38f; mx[mi][1] = -3.4e38f; }
#pragma unroll
        for (int mi = 0; mi < 4; mi++)
#pragma unroll
            for (int ni = 0; ni < 4; ni++)
#pragma unroll
                for (int r = 0; r < 4; r++) {
                    float v = acc[mi][ni][r] + bv[mi][r >> 1];
                    mx[mi][r >> 1] = fmaxf(mx[mi][r >> 1], v);
                    lsum += v; lsq += v * v;
                }
#pragma unroll
        for (int mi = 0; mi < 4; mi++)
#pragma unroll
            for (int h = 0; h < 2; h++) {
                float m0 = mx[mi][h];
                m0 = fmaxf(m0, __shfl_xor_sync(0xFFFFFFFF, m0, 1));
                m0 = fmaxf(m0, __shfl_xor_sync(0xFFFFFFFF, m0, 2));
                mx[mi][h] = m0;
            }
        if (t == 0) {
#pragma unroll
            for (int mi = 0; mi < 4; mi++) {
                sMax[wn][mbase + mi * 16 + g] = mx[mi][0];
                sMax[wn][mbase + mi * 16 + g + 8] = mx[mi][1];
            }
        }
    }

    sRs[tid] = lsum; sRq[tid] = lsq;
    __syncthreads();
    for (int o = 128; o > 0; o >>= 1) {
        if (tid < o) { sRs[tid] += sRs[tid + o]; sRq[tid] += sRq[tid + o]; }
        __syncthreads();
    }
    if (tid == 0) {
        part[(inst * NTILE + tile) * 2 + 0] = sRs[0];
        part[(inst * NTILE + tile) * 2 + 1] = sRq[0];
    }
    if (!yout && tid < 128) {
        float m0 = fmaxf(fmaxf(sMax[0][tid], sMax[1][tid]),
                         fmaxf(sMax[2][tid], sMax[3][tid]));
        pmax[(inst * NTILE + tile) * HID + tid] = m0;
    }
}

// ---------------- LN stat finalize (one block per instance) ------------------
__global__ void ln_finalize(const float* __restrict__ part, float* __restrict__ stats) {
    const int inst = blockIdx.x, t = threadIdx.x;   // 32 threads
    float s = part[(inst * NTILE + t) * 2 + 0];
    float q = part[(inst * NTILE + t) * 2 + 1];
#pragma unroll
    for (int o = 16; o > 0; o >>= 1) {
        s += __shfl_xor_sync(0xFFFFFFFF, s, o);
        q += __shfl_xor_sync(0xFFFFFFFF, q, o);
    }
    if (t == 0) {
        const float n = (float)LNE;
        float m = s / n;
        float var = (q - s * s / n) / (n - 1.0f);
        var = fmaxf(var, 0.f);
        stats[inst * 2 + 0] = m;
        stats[inst * 2 + 1] = 1.0f / (sqrtf(var) + 1e-5f);
    }
}

// ---------------- head: tile-max reduce, LN2+relu, FC ------------------------
__global__ void head_kernel(const float* __restrict__ pmax, const float* __restrict__ stats,
                            const float* __restrict__ Wmu, const float* __restrict__ bmu,
                            const float* __restrict__ Wlv, const float* __restrict__ blv,
                            float* __restrict__ out) {
    __shared__ float comb[2 * HID];
    const int b = blockIdx.x, t = threadIdx.x;   // 128 threads
    for (int enc = 0; enc < 2; enc++) {
        int inst = enc * BATCH + b;
        float mx = 0.f;                           // null column raw value
        for (int tl = 0; tl < NTILE; tl++)
            mx = fmaxf(mx, pmax[(inst * NTILE + tl) * HID + t]);
        float v = (mx - stats[inst * 2 + 0]) * stats[inst * 2 + 1];
        comb[enc * HID + t] = fmaxf(v, 0.f);
    }
    __syncthreads();
    const float* Wt; const float* bt; float* op; int l;
    if (t < LAT) { Wt = Wmu; bt = bmu; op = out;               l = t; }
    else         { Wt = Wlv; bt = blv; op = out + BATCH * LAT; l = t - LAT; }
    float s = bt[l];
#pragma unroll 8
    for (int j = 0; j < 2 * HID; j++) s += comb[j] * Wt[l * 2 * HID + j];
    op[b * LAT + l] = s;
}

// ---------------- driver -----------------------------------------------------
extern "C" void kernel_launch(void* const* d_in, const int* in_sizes, int n_in,
                              void* d_out, int out_size) {
    const float* lf  = (const float*)d_in[0];
    const float* pf  = (const float*)d_in[1];
    const int*   ch  = (const int*)d_in[2];
    const float* Wl1 = (const float*)d_in[3];
    const float* bl1 = (const float*)d_in[4];
    const float* Wl2 = (const float*)d_in[5];
    const float* bl2 = (const float*)d_in[6];
    const float* Wp1 = (const float*)d_in[7];
    const float* bp1 = (const float*)d_in[8];
    const float* Wp2 = (const float*)d_in[9];
    const float* bp2 = (const float*)d_in[10];
    const float* Wmu = (const float*)d_in[11];
    const float* bmu = (const float*)d_in[12];
    const float* Wlv = (const float*)d_in[13];
    const float* blv = (const float*)d_in[14];
    float* out = (float*)d_out;

    __half *xt, *y1, *Wa1, *Wa2;
    float *p1, *p2, *st1, *st2, *pmax;
    cudaGetSymbolAddress((void**)&xt,   g_xt);
    cudaGetSymbolAddress((void**)&y1,   g_y1);
    cudaGetSymbolAddress((void**)&Wa1,  g_Wa1);
    cudaGetSymbolAddress((void**)&Wa2,  g_Wa2);
    cudaGetSymbolAddress((void**)&p1,   g_part1);
    cudaGetSymbolAddress((void**)&p2,   g_part2);
    cudaGetSymbolAddress((void**)&st1,  g_st1);
    cudaGetSymbolAddress((void**)&st2,  g_st2);
    cudaGetSymbolAddress((void**)&pmax, g_pmax);

    cudaFuncSetAttribute(conv_tc<CIN, false>,
                         cudaFuncAttributeMaxDynamicSharedMemorySize, DSMEM_BYTES);
    cudaFuncSetAttribute(conv_tc<HID, true>,
                         cudaFuncAttributeMaxDynamicSharedMemorySize, DSMEM_BYTES);

    // launch order fixed so conv2 is ncu launch index 5 (-s 5 -c 1)
    prep_weights1<<<96, 512>>>(Wl1, Wp1);                                    // 0
    prep_weights2<<<96, 512>>>(Wl2, Wp2);                                    // 1
    transpose_kernel<<<dim3((NNODE + 31) / 32, 2, NINST), dim3(32, 8)>>>(lf, pf); // 2

    conv_tc<CIN, false><<<dim3(NTILE, BATCH, 2), 256, DSMEM_BYTES>>>(
        xt, Wa1, bl1, bp1, ch, nullptr, y1, p1, nullptr);                    // 3
    ln_finalize<<<NINST, 32>>>(p1, st1);                                     // 4
    conv_tc<HID, true><<<dim3(NTILE, BATCH, 2), 256, DSMEM_BYTES>>>(
        y1, Wa2, bl2, bp2, ch, st1, nullptr, p2, pmax);                      // 5
    ln_finalize<<<NINST, 32>>>(p2, st2);                                     // 6
    head_kernel<<<BATCH, 128>>>(pmax, st2, Wmu, bmu, Wlv, blv, out);         // 7
}

// round 15
// speedup vs baseline: 1.0455x; 1.0455x over previous
#include <cuda_runtime.h>
#include <cuda_fp16.h>
#include <cstdint>

#define BATCH 64
#define CIN   64
#define NNODE 4097
#define TNODE 4096
#define HID   128
#define LAT   64
#define NINST 128
#define NTILE 32                 // 4096 nodes / 128-node tiles
#define LNE   (NNODE*HID)
#define SMSH  72                 // smem row stride in halves (144B, LDSM conflict-free)
#define DSMEM_BYTES (4 * 128 * SMSH * 2)   // 73728 B
#define TILE_STEP (16 * SMSH * 2)   // bytes between 16-row tiles in smem
#define STDS  136                // epilogue staging stride in halves (272B)

// ---------------- scratch ----------------------------------------------------
__device__ __half g_xt [(size_t)NINST * NNODE * CIN];
__device__ __half g_y1 [(size_t)NINST * NNODE * HID];
__device__ __half g_Wa1[2 * HID * 3 * CIN];    // [enc][o][k], k = k3*C + c
__device__ __half g_Wa2[2 * HID * 3 * HID];
__device__ float g_part1[NINST * NTILE * 2];
__device__ float g_part2[NINST * NTILE * 2];
__device__ float g_st1[NINST * 2];
__device__ float g_st2[NINST * 2];
__device__ float g_pmax[NINST * NTILE * HID];

__device__ __forceinline__ void mma_f16(float* d, const uint32_t* a, uint32_t b0, uint32_t b1) {
    asm volatile(
        "mma.sync.aligned.m16n8k16.row.col.f32.f16.f16.f32 "
        "{%0,%1,%2,%3}, {%4,%5,%6,%7}, {%8,%9}, {%0,%1,%2,%3};"
        : "+f"(d[0]), "+f"(d[1]), "+f"(d[2]), "+f"(d[3])
        : "r"(a[0]), "r"(a[1]), "r"(a[2]), "r"(a[3]), "r"(b0), "r"(b1));
}
__device__ __forceinline__ void ldsm4(uint32_t* r, uint32_t addr) {
    asm volatile("ldmatrix.sync.aligned.m8n8.x4.shared.b16 {%0,%1,%2,%3}, [%4];"
                 : "=r"(r[0]), "=r"(r[1]), "=r"(r[2]), "=r"(r[3]) : "r"(addr));
}
__device__ __forceinline__ void stsm4t(uint32_t addr, uint32_t r0, uint32_t r1,
                                       uint32_t r2, uint32_t r3) {
    asm volatile("stmatrix.sync.aligned.m8n8.x4.trans.shared.b16 [%0], {%1,%2,%3,%4};"
                 :: "r"(addr), "r"(r0), "r"(r1), "r"(r2), "r"(r3) : "memory");
}
__device__ __forceinline__ uint32_t smem_u32(const void* p) {
    uint32_t a;
    asm("{ .reg .u64 t; cvta.to.shared.u64 t, %1; cvt.u32.u64 %0, t; }" : "=r"(a) : "l"(p));
    return a;
}
__device__ __forceinline__ void cp16(uint32_t dst, const void* src) {
    asm volatile("cp.async.ca.shared.global [%0], [%1], 16;" :: "r"(dst), "l"(src));
}
__device__ __forceinline__ void cp_commit() { asm volatile("cp.async.commit_group;"); }
template <int N>
__device__ __forceinline__ void cp_wait() { asm volatile("cp.async.wait_group %0;" :: "n"(N)); }
__device__ __forceinline__ uint32_t packh2(float x, float y) {
    __half2 h = __floats2half2_rn(x, y);
    return *reinterpret_cast<const uint32_t*>(&h);
}

// ---------------- weight reorder + fp16 round (two launches for ncu indexing)
__global__ void prep_weights1(const float* __restrict__ Wl1, const float* __restrict__ Wp1) {
    int idx = blockIdx.x * blockDim.x + threadIdx.x;
    int stride = gridDim.x * blockDim.x;
    for (int i = idx; i < 2 * HID * 3 * CIN; i += stride) {
        int enc = i / (HID * 3 * CIN);
        int rem = i % (HID * 3 * CIN);
        int o = rem / (3 * CIN), k = rem % (3 * CIN);
        int k3 = k / CIN, c = k % CIN;
        g_Wa1[i] = __float2half_rn((enc ? Wp1 : Wl1)[(o * CIN + c) * 3 + k3]);
    }
}
__global__ void prep_weights2(const float* __restrict__ Wl2, const float* __restrict__ Wp2) {
    int idx = blockIdx.x * blockDim.x + threadIdx.x;
    int stride = gridDim.x * blockDim.x;
    for (int i = idx; i < 2 * HID * 3 * HID; i += stride) {
        int enc = i / (HID * 3 * HID);
        int rem = i % (HID * 3 * HID);
        int o = rem / (3 * HID), k = rem % (3 * HID);
        int k3 = k / HID, c = k % HID;
        g_Wa2[i] = __float2half_rn((enc ? Wp2 : Wl2)[(o * HID + c) * 3 + k3]);
    }
}

// ---------------- transpose feats (B,C,N)->(inst,N,C), fp16 ------------------
__global__ void transpose_kernel(const float* __restrict__ lf, const float* __restrict__ pf) {
    __shared__ float tile[32][33];
    int inst = blockIdx.z;
    int enc = inst >> 6, b = inst & 63;
    const float* src = (enc ? pf : lf) + (size_t)b * CIN * NNODE;
    int n0 = blockIdx.x * 32, c0 = blockIdx.y * 32;
    for (int i = threadIdx.y; i < 32; i += 8) {
        int c = c0 + i, n = n0 + threadIdx.x;
        if (c < CIN && n < NNODE) tile[i][threadIdx.x] = src[(size_t)c * NNODE + n];
    }
    __syncthreads();
    __half* dst = g_xt + (size_t)inst * NNODE * CIN;
    for (int i = threadIdx.y; i < 32; i += 8) {
        int n = n0 + i, c = c0 + threadIdx.x;
        if (n < NNODE && c < CIN)
            dst[(size_t)n * CIN + c] = __float2half_rn(tile[threadIdx.x][i]);
    }
}

// ---------------- tensor-core tree conv (fp16 mma + ldmatrix, K=64 chunks) ---
// D[m][n] = sum_k W[m][k] * G[n][k];  8 warps, warp tile 64(M)x32(N)
template <int C, bool LN>
__global__ void __launch_bounds__(256, 2) conv_tc(
        const __half* __restrict__ xin, const __half* __restrict__ Wa,
        const float* __restrict__ bias0, const float* __restrict__ bias1,
        const int* __restrict__ children,
        const float* __restrict__ stats,
        __half* __restrict__ yout,           // conv1: raw fp16 output; conv2: null
        float* __restrict__ part,            // per-tile (sum, sumsq)
        float* __restrict__ pmax) {          // conv2: per-tile per-channel max
    constexpr int K = 3 * C;
    constexpr int NCH = K / 64;              // 64-half K chunks

    extern __shared__ __half dynH[];
    __half* sAbuf[2] = { dynH,                 dynH + 128 * SMSH };
    __half* sBbuf[2] = { dynH + 2 * 128 * SMSH, dynH + 3 * 128 * SMSH };
    __shared__ int   sCh[384];
    __shared__ float sRed[16];
    __shared__ float sMax[4][128];

    const int tid = threadIdx.x;
    const int w = tid >> 5, lane = tid & 31;
    const int g = lane >> 2, t = lane & 3;
    const int wm = w >> 2, wn = w & 3;
    const int mbase = wm * 64, nbase = wn * 32;

    // ldmatrix address roles (mapping verified in R8-R12 runs)
    const int lr = lane & 7, lm = lane >> 3;
    const int arow = ((lm & 1) << 3) + lr, acol = (lm >> 1) << 3;
    const int brow = ((lm >> 1) << 3) + lr, bcol = (lm & 1) << 3;
    const uint32_t aRel = ((mbase + arow) * SMSH + acol) * 2;
    const uint32_t bRel = ((nbase + brow) * SMSH + bcol) * 2;

    const int enc = blockIdx.z, b = blockIdx.y, tile = blockIdx.x;
    const int inst = enc * BATCH + b;
    const int n0 = 1 + tile * 128;

    const int* csrc = children + (size_t)b * 3 * TNODE + 3 * (n0 - 1);
    sCh[tid] = csrc[tid];
    if (tid < 128) sCh[256 + tid] = csrc[256 + tid];

    float mean = 0.f, inv = 0.f;
    if (LN) { mean = stats[inst * 2 + 0]; inv = stats[inst * 2 + 1]; }

    const __half* xb = xin + (size_t)inst * NNODE * C;
    const __half* Wb = Wa + (size_t)enc * HID * K;
    const float* bb = enc ? bias1 : bias0;

    const int row = tid >> 1, hsel = tid & 1;     // fill role: row x 32-half half
    const uint32_t aAddr[2] = { smem_u32(sAbuf[0]) + (row * SMSH + hsel * 32) * 2,
                                smem_u32(sAbuf[1]) + (row * SMSH + hsel * 32) * 2 };
    const uint32_t bAddr[2] = { smem_u32(sBbuf[0]) + (row * SMSH + hsel * 32) * 2,
                                smem_u32(sBbuf[1]) + (row * SMSH + hsel * 32) * 2 };

    float acc[4][4][4];
#pragma unroll
    for (int mi = 0; mi < 4; mi++)
#pragma unroll
        for (int ni = 0; ni < 4; ni++)
#pragma unroll
            for (int r = 0; r < 4; r++) acc[mi][ni][r] = 0.f;

    __syncthreads();   // sCh ready

    // ---- fill helpers (64-half chunks) --------------------------------------
    auto fillA = [&](int ck, int buf) {
        const __half* src = Wb + (size_t)row * K + ck * 64 + hsel * 32;
#pragma unroll
        for (int j = 0; j < 4; j++) cp16(aAddr[buf] + j * 16, src + j * 8);
    };
    auto fillB_cp = [&](int ck, int buf) {        // conv1: raw fp16 copy
        const int kch = (ck * 64) / C, cb = (ck * 64) % C;
        const int chd = sCh[row * 3 + kch];
        const __half* src = xb + (size_t)chd * C + cb + hsel * 32;
#pragma unroll
        for (int j = 0; j < 4; j++) cp16(bAddr[buf] + j * 16, src + j * 8);
    };
    uint4 breg[4];
    auto ldgB = [&](int ck) {                     // conv2: stage to regs
        const int kch = (ck * 64) / C, cb = (ck * 64) % C;
        const int chd = sCh[row * 3 + kch];
        const uint4* src = reinterpret_cast<const uint4*>(xb + (size_t)chd * C + cb + hsel * 32);
#pragma unroll
        for (int j = 0; j < 4; j++) breg[j] = src[j];
    };
    auto storeB = [&](int buf) {                  // conv2: LN+relu -> smem fp16
        uint32_t base = bAddr[buf];
#pragma unroll
        for (int j = 0; j < 4; j++) {
            uint32_t o[4];
#pragma unroll
            for (int q = 0; q < 4; q++) {
                uint32_t raw = reinterpret_cast<const uint32_t*>(&breg[j])[q];
                __half2 h = *reinterpret_cast<const __half2*>(&raw);
                float2 f = __half22float2(h);
                f.x = fmaxf((f.x - mean) * inv, 0.f);
                f.y = fmaxf((f.y - mean) * inv, 0.f);
                o[q] = packh2(f.x, f.y);
            }
            asm volatile("st.shared.v4.b32 [%0], {%1,%2,%3,%4};"
                         :: "r"(base + j * 16), "r"(o[0]), "r"(o[1]), "r"(o[2]), "r"(o[3]));
        }
    };
    auto mmaChunk = [&](int buf) {
        const uint32_t aB = smem_u32(sAbuf[buf]) + aRel;
        const uint32_t bB = smem_u32(sBbuf[buf]) + bRel;
#pragma unroll
        for (int ks = 0; ks < 4; ks++) {
            uint32_t af[4][4], bf[2][4];
#pragma unroll
            for (int mi = 0; mi < 4; mi++) ldsm4(af[mi], aB + mi * TILE_STEP + ks * 32);
#pragma unroll
            for (int p = 0; p < 2; p++)   ldsm4(bf[p], bB + p * TILE_STEP + ks * 32);
#pragma unroll
            for (int mi = 0; mi < 4; mi++)
#pragma unroll
                for (int p = 0; p < 2; p++) {
                    mma_f16(acc[mi][2 * p + 0], af[mi], bf[p][0], bf[p][1]);
                    mma_f16(acc[mi][2 * p + 1], af[mi], bf[p][2], bf[p][3]);
                }
        }
    };

    // ---- pipelined main loop ------------------------------------------------
    if (!LN) {
        fillA(0, 0); fillB_cp(0, 0); cp_commit();
#pragma unroll 1
        for (int ck = 0; ck < NCH; ck++) {
            if (ck + 1 < NCH) {
                fillA(ck + 1, (ck + 1) & 1);
                fillB_cp(ck + 1, (ck + 1) & 1);
                cp_commit();
                cp_wait<1>();
            } else cp_wait<0>();
            __syncthreads();
            mmaChunk(ck & 1);
            __syncthreads();
        }
    } else {
        fillA(0, 0); cp_commit();
        ldgB(0); storeB(0);
#pragma unroll 1
        for (int ck = 0; ck < NCH; ck++) {
            const bool hn = (ck + 1 < NCH);
            if (hn) {
                fillA(ck + 1, (ck + 1) & 1);
                cp_commit();
                ldgB(ck + 1);
                cp_wait<1>();
            } else cp_wait<0>();
            __syncthreads();
            mmaChunk(ck & 1);
            __syncthreads();
            if (hn) storeB((ck + 1) & 1);
        }
    }

    // ---------------- epilogue ------------------------------------------------
    float bv[4][2];
#pragma unroll
    for (int mi = 0; mi < 4; mi++) {
        bv[mi][0] = bb[mbase + mi * 16 + g];
        bv[mi][1] = bb[mbase + mi * 16 + g + 8];
    }
    float lsum = 0.f, lsq = 0.f;

    if (yout) {
        // stage D (with bias, fp16) into smem node-major via stmatrix.trans,
        // then write y1 with coalesced 128B rows.
        const uint32_t stBase = smem_u32(dynH);
        const uint32_t stRel = ((uint32_t)(nbase + ((lm >> 1) << 3) + lr) * STDS
                                + mbase + ((lm & 1) << 3)) * 2;
#pragma unroll
        for (int mi = 0; mi < 4; mi++)
#pragma unroll
            for (int np = 0; np < 2; np++) {
                const int ni0 = 2 * np, ni1 = 2 * np + 1;
                float v00 = acc[mi][ni0][0] + bv[mi][0], v01 = acc[mi][ni0][1] + bv[mi][0];
                float v02 = acc[mi][ni0][2] + bv[mi][1], v03 = acc[mi][ni0][3] + bv[mi][1];
                float v10 = acc[mi][ni1][0] + bv[mi][0], v11 = acc[mi][ni1][1] + bv[mi][0];
                float v12 = acc[mi][ni1][2] + bv[mi][1], v13 = acc[mi][ni1][3] + bv[mi][1];
                lsum += v00 + v01 + v02 + v03 + v10 + v11 + v12 + v13;
                lsq  += v00*v00 + v01*v01 + v02*v02 + v03*v03
                      + v10*v10 + v11*v11 + v12*v12 + v13*v13;
                stsm4t(stBase + stRel + (np * 16 * STDS + mi * 16) * 2,
                       packh2(v00, v01), packh2(v02, v03),
                       packh2(v10, v11), packh2(v12, v13));
            }
        __syncthreads();
        {
            const int rr = tid >> 1, hh = tid & 1;      // node row, 64-half half
            __half* yb = yout + ((size_t)inst * NNODE + n0 + rr) * HID + hh * 64;
            const uint4* s = reinterpret_cast<const uint4*>(dynH + rr * STDS + hh * 64);
            uint4* d = reinterpret_cast<uint4*>(yb);
#pragma unroll
            for (int j = 0; j < 8; j++) d[j] = s[j];
        }
        if (tile == 0 && tid < 16)
            reinterpret_cast<float4*>(yout + (size_t)inst * NNODE * HID)[tid] =
                make_float4(0.f, 0.f, 0.f, 0.f);
    } else {
        float mx[4][2];
#pragma unroll
        for (int mi = 0; mi < 4; mi++) { mx[mi][0] = -3.4e38f; mx[mi][1] = -3.4e38f; }
#pragma unroll
        for (int mi = 0; mi < 4; mi++)
#pragma unroll
            for (int ni = 0; ni < 4; ni++)
#pragma unroll
                for (int r = 0; r < 4; r++) {
                    float v = acc[mi][ni][r] + bv[mi][r >> 1];
                    mx[mi][r >> 1] = fmaxf(mx[mi][r >> 1], v);
                    lsum += v; lsq += v * v;
                }
#pragma unroll
        for (int mi = 0; mi < 4; mi++)
#pragma unroll
            for (int h = 0; h < 2; h++) {
                float m0 = mx[mi][h];
                m0 = fmaxf(m0, __shfl_xor_sync(0xFFFFFFFF, m0, 1));
                m0 = fmaxf(m0, __shfl_xor_sync(0xFFFFFFFF, m0, 2));
                mx[mi][h] = m0;
            }
        if (t == 0) {
#pragma unroll
            for (int mi = 0; mi < 4; mi++) {
                sMax[wn][mbase + mi * 16 + g] = mx[mi][0];
                sMax[wn][mbase + mi * 16 + g + 8] = mx[mi][1];
            }
        }
    }

    // ---- block (sum, sumsq) reduction: warp shuffle + single sync -----------
#pragma unroll
    for (int o = 16; o > 0; o >>= 1) {
        lsum += __shfl_xor_sync(0xFFFFFFFF, lsum, o);
        lsq  += __shfl_xor_sync(0xFFFFFFFF, lsq, o);
    }
    if (lane == 0) { sRed[w] = lsum; sRed[8 + w] = lsq; }
    __syncthreads();
    if (tid == 0) {
        float s = 0.f, q = 0.f;
#pragma unroll
        for (int j = 0; j < 8; j++) { s += sRed[j]; q += sRed[8 + j]; }
        part[(inst * NTILE + tile) * 2 + 0] = s;
        part[(inst * NTILE + tile) * 2 + 1] = q;
    }
    if (!yout && tid < 128) {
        float m0 = fmaxf(fmaxf(sMax[0][tid], sMax[1][tid]),
                         fmaxf(sMax[2][tid], sMax[3][tid]));
        pmax[(inst * NTILE + tile) * HID + tid] = m0;
    }
}

// ---------------- LN stat finalize (one block per instance) ------------------
__global__ void ln_finalize(const float* __restrict__ part, float* __restrict__ stats) {
    const int inst = blockIdx.x, t = threadIdx.x;   // 32 threads
    float s = part[(inst * NTILE + t) * 2 + 0];
    float q = part[(inst * NTILE + t) * 2 + 1];
#pragma unroll
    for (int o = 16; o > 0; o >>= 1) {
        s += __shfl_xor_sync(0xFFFFFFFF, s, o);
        q += __shfl_xor_sync(0xFFFFFFFF, q, o);
    }
    if (t == 0) {
        const float n = (float)LNE;
        float m = s / n;
        float var = (q - s * s / n) / (n - 1.0f);
        var = fmaxf(var, 0.f);
        stats[inst * 2 + 0] = m;
        stats[inst * 2 + 1] = 1.0f / (sqrtf(var) + 1e-5f);
    }
}

// ---------------- head: tile-max reduce, LN2+relu, FC ------------------------
__global__ void head_kernel(const float* __restrict__ pmax, const float* __restrict__ stats,
                            const float* __restrict__ Wmu, const float* __restrict__ bmu,
                            const float* __restrict__ Wlv, const float* __restrict__ blv,
                            float* __restrict__ out) {
    __shared__ float comb[2 * HID];
    const int b = blockIdx.x, t = threadIdx.x;   // 128 threads
    for (int enc = 0; enc < 2; enc++) {
        int inst = enc * BATCH + b;
        float mx = 0.f;                           // null column raw value
        for (int tl = 0; tl < NTILE; tl++)
            mx = fmaxf(mx, pmax[(inst * NTILE + tl) * HID + t]);
        float v = (mx - stats[inst * 2 + 0]) * stats[inst * 2 + 1];
        comb[enc * HID + t] = fmaxf(v, 0.f);
    }
    __syncthreads();
    const float* Wt; const float* bt; float* op; int l;
    if (t < LAT) { Wt = Wmu; bt = bmu; op = out;               l = t; }
    else         { Wt = Wlv; bt = blv; op = out + BATCH * LAT; l = t - LAT; }
    float s = bt[l];
#pragma unroll 8
    for (int j = 0; j < 2 * HID; j++) s += comb[j] * Wt[l * 2 * HID + j];
    op[b * LAT + l] = s;
}

// ---------------- driver -----------------------------------------------------
extern "C" void kernel_launch(void* const* d_in, const int* in_sizes, int n_in,
                              void* d_out, int out_size) {
    const float* lf  = (const float*)d_in[0];
    const float* pf  = (const float*)d_in[1];
    const int*   ch  = (const int*)d_in[2];
    const float* Wl1 = (const float*)d_in[3];
    const float* bl1 = (const float*)d_in[4];
    const float* Wl2 = (const float*)d_in[5];
    const float* bl2 = (const float*)d_in[6];
    const float* Wp1 = (const float*)d_in[7];
    const float* bp1 = (const float*)d_in[8];
    const float* Wp2 = (const float*)d_in[9];
    const float* bp2 = (const float*)d_in[10];
    const float* Wmu = (const float*)d_in[11];
    const float* bmu = (const float*)d_in[12];
    const float* Wlv = (const float*)d_in[13];
    const float* blv = (const float*)d_in[14];
    float* out = (float*)d_out;

    __half *xt, *y1, *Wa1, *Wa2;
    float *p1, *p2, *st1, *st2, *pmax;
    cudaGetSymbolAddress((void**)&xt,   g_xt);
    cudaGetSymbolAddress((void**)&y1,   g_y1);
    cudaGetSymbolAddress((void**)&Wa1,  g_Wa1);
    cudaGetSymbolAddress((void**)&Wa2,  g_Wa2);
    cudaGetSymbolAddress((void**)&p1,   g_part1);
    cudaGetSymbolAddress((void**)&p2,   g_part2);
    cudaGetSymbolAddress((void**)&st1,  g_st1);
    cudaGetSymbolAddress((void**)&st2,  g_st2);
    cudaGetSymbolAddress((void**)&pmax, g_pmax);

    cudaFuncSetAttribute(conv_tc<CIN, false>,
                         cudaFuncAttributeMaxDynamicSharedMemorySize, DSMEM_BYTES);
    cudaFuncSetAttribute(conv_tc<HID, true>,
                         cudaFuncAttributeMaxDynamicSharedMemorySize, DSMEM_BYTES);

    // launch order fixed so conv2 is ncu launch index 5 (-s 5 -c 1)
    prep_weights1<<<96, 512>>>(Wl1, Wp1);                                    // 0
    prep_weights2<<<96, 512>>>(Wl2, Wp2);                                    // 1
    transpose_kernel<<<dim3((NNODE + 31) / 32, 2, NINST), dim3(32, 8)>>>(lf, pf); // 2

    conv_tc<CIN, false><<<dim3(NTILE, BATCH, 2), 256, DSMEM_BYTES>>>(
        xt, Wa1, bl1, bp1, ch, nullptr, y1, p1, nullptr);                    // 3
    ln_finalize<<<NINST, 32>>>(p1, st1);                                     // 4
    conv_tc<HID, true><<<dim3(NTILE, BATCH, 2), 256, DSMEM_BYTES>>>(
        y1, Wa2, bl2, bp2, ch, st1, nullptr, p2, pmax);                      // 5
    ln_finalize<<<NINST, 32>>>(p2, st2);                                     // 6
    head_kernel<<<BATCH, 128>>>(pmax, st2, Wmu, bmu, Wlv, blv, out);         // 7
}